// round 12
// baseline (speedup 1.0000x reference)
#include <cuda_runtime.h>
#include <math_constants.h>

// Single-query attention: y = softmax(K @ q) @ V   (fp32, M=131072, D=256)
// Pass1: persistent single-wave (592 = 148 SM x 4 CTAs). cp.async (LDGSTS)
// double-buffered smem staging of 8-row K/V chunks: loads flow through the
// async engine independent of warp compute stalls (registers untouched, so
// 4 CTAs/SM is preserved). Compute reads staged smem (29cyc LDS).
// Tail: R11's flat kernel (front-issued loads, joint reduction), unchanged.

#define M_TOTAL   131072
#define DIM       256
#define NCTA      592                      // 148 * 4, one wave
#define NWARPS    8
#define CHUNK_ROWS 8                       // one row per warp per chunk
#define CHUNK_FLOATS (CHUNK_ROWS * DIM)    // 2048 floats = 8KB
#define NCHUNKS   (M_TOTAL / CHUNK_ROWS)   // 16384

// Scratch (allocation-free): ~620 KB
__device__ float  g_partT[DIM][NCTA];      // transposed: [column][cta]
__device__ float2 g_ml[NCTA];              // packed (m, l)

__device__ __forceinline__ void cp16(float4* s, const float4* g) {
    unsigned int sa = (unsigned int)__cvta_generic_to_shared(s);
    asm volatile("cp.async.cg.shared.global [%0], [%1], 16;" :: "r"(sa), "l"(g));
}
#define CP_COMMIT() asm volatile("cp.async.commit_group;" ::: "memory")
#define CP_WAIT1()  asm volatile("cp.async.wait_group 1;" ::: "memory")

__global__ __launch_bounds__(256, 4)
void sqa_pass1(const float* __restrict__ q,
               const float* __restrict__ K,
               const float* __restrict__ V) {
    const int tid  = threadIdx.x;
    const int warp = tid >> 5;
    const int lane = tid & 31;
    const int bid  = blockIdx.x;

    // Double-buffered staging: 2 x (8KB K + 8KB V) = 32KB static
    __shared__ float4 sK[2][CHUNK_FLOATS / 4];
    __shared__ float4 sV[2][CHUNK_FLOATS / 4];

    const float4 q0 = reinterpret_cast<const float4*>(q)[lane];
    const float4 q1 = reinterpret_cast<const float4*>(q)[lane + 32];

    float m = -CUDART_INF_F;
    float l = 0.0f;
    float4 a0 = make_float4(0.f, 0.f, 0.f, 0.f);
    float4 a1 = make_float4(0.f, 0.f, 0.f, 0.f);

    // ---- prefetch first chunk ----
    {
        const float4* gk = reinterpret_cast<const float4*>(K) + (size_t)bid * (CHUNK_FLOATS / 4);
        const float4* gv = reinterpret_cast<const float4*>(V) + (size_t)bid * (CHUNK_FLOATS / 4);
        cp16(&sK[0][tid],       gk + tid);
        cp16(&sK[0][tid + 256], gk + tid + 256);
        cp16(&sV[0][tid],       gv + tid);
        cp16(&sV[0][tid + 256], gv + tid + 256);
    }
    CP_COMMIT();

    int buf = 0;
    for (int c = bid; c < NCHUNKS; c += NCTA, buf ^= 1) {
        // prefetch next chunk into the other buffer (consumed 1 iter ago)
        const int cn = c + NCTA;
        if (cn < NCHUNKS) {
            const float4* gk = reinterpret_cast<const float4*>(K) + (size_t)cn * (CHUNK_FLOATS / 4);
            const float4* gv = reinterpret_cast<const float4*>(V) + (size_t)cn * (CHUNK_FLOATS / 4);
            cp16(&sK[buf ^ 1][tid],       gk + tid);
            cp16(&sK[buf ^ 1][tid + 256], gk + tid + 256);
            cp16(&sV[buf ^ 1][tid],       gv + tid);
            cp16(&sV[buf ^ 1][tid + 256], gv + tid + 256);
        }
        CP_COMMIT();
        CP_WAIT1();        // current buffer's fill group complete
        __syncthreads();   // make staged data visible across threads

        // ---- compute: warp w handles row w of the chunk ----
        const float4* kr = &sK[buf][warp * (DIM / 4)];
        const float4  kA = kr[lane];
        const float4  kB = kr[lane + 32];

        float dd = kA.x * q0.x + kA.y * q0.y + kA.z * q0.z + kA.w * q0.w
                 + kB.x * q1.x + kB.y * q1.y + kB.z * q1.z + kB.w * q1.w;
        #pragma unroll
        for (int off = 16; off > 0; off >>= 1)
            dd += __shfl_xor_sync(0xffffffffu, dd, off);

        const float mnew  = fmaxf(m, dd);
        const float scale = __expf(m - mnew);   // exp(-inf)=0 on first chunk
        const float wv    = __expf(dd - mnew);
        l = l * scale + wv;
        m = mnew;

        const float4* vr = &sV[buf][warp * (DIM / 4)];
        const float4  vA = vr[lane];
        const float4  vB = vr[lane + 32];

        a0.x = a0.x * scale + wv * vA.x;
        a0.y = a0.y * scale + wv * vA.y;
        a0.z = a0.z * scale + wv * vA.z;
        a0.w = a0.w * scale + wv * vA.w;
        a1.x = a1.x * scale + wv * vB.x;
        a1.y = a1.y * scale + wv * vB.y;
        a1.z = a1.z * scale + wv * vB.z;
        a1.w = a1.w * scale + wv * vB.w;

        __syncthreads();   // all reads done before buffer is overwritten
    }

    // ---------------- Merge 8 warps within the CTA ------------------------
    __shared__ float s_m[NWARPS];
    __shared__ float s_l[NWARPS];
    __shared__ float s_acc[NWARPS][DIM];

    if (lane == 0) { s_m[warp] = m; s_l[warp] = l; }
    float* dst = s_acc[warp];
    dst[lane * 4 + 0]       = a0.x;
    dst[lane * 4 + 1]       = a0.y;
    dst[lane * 4 + 2]       = a0.z;
    dst[lane * 4 + 3]       = a0.w;
    dst[128 + lane * 4 + 0] = a1.x;
    dst[128 + lane * 4 + 1] = a1.y;
    dst[128 + lane * 4 + 2] = a1.z;
    dst[128 + lane * 4 + 3] = a1.w;
    __syncthreads();

    float bm = s_m[0];
    #pragma unroll
    for (int w2 = 1; w2 < NWARPS; ++w2) bm = fmaxf(bm, s_m[w2]);

    float y = 0.0f;
    float L = 0.0f;
    #pragma unroll
    for (int w2 = 0; w2 < NWARPS; ++w2) {
        const float sf = __expf(s_m[w2] - bm);
        y += s_acc[w2][tid] * sf;
        L += s_l[w2] * sf;
    }

    g_partT[tid][bid] = y;
    if (tid == 0) g_ml[bid] = make_float2(bm, L);
}

// Tail: 256 blocks (one per output column) x 256 threads (R11, unchanged).
__global__ __launch_bounds__(256)
void sqa_tail(float* __restrict__ out) {
    const int t    = threadIdx.x;
    const int warp = t >> 5;
    const int lane = t & 31;
    const int c    = blockIdx.x;

    __shared__ float s8m[NWARPS];
    __shared__ float s8l[NWARPS];
    __shared__ float s8a[NWARPS];

    const bool has3 = (t < NCTA - 512);

    const float2 ml0 = g_ml[t];
    const float2 ml1 = g_ml[t + 256];
    const float2 ml2 = has3 ? g_ml[t + 512] : make_float2(-CUDART_INF_F, 0.0f);
    const float* row = g_partT[c];
    const float  r0  = row[t];
    const float  r1  = row[t + 256];
    const float  r2  = has3 ? row[t + 512] : 0.0f;

    float mv = fmaxf(fmaxf(ml0.x, ml1.x), ml2.x);
    #pragma unroll
    for (int off = 16; off > 0; off >>= 1)
        mv = fmaxf(mv, __shfl_xor_sync(0xffffffffu, mv, off));
    if (lane == 0) s8m[warp] = mv;
    __syncthreads();
    const float gmax = fmaxf(fmaxf(fmaxf(s8m[0], s8m[1]), fmaxf(s8m[2], s8m[3])),
                             fmaxf(fmaxf(s8m[4], s8m[5]), fmaxf(s8m[6], s8m[7])));

    const float e0 = __expf(ml0.x - gmax);
    const float e1 = __expf(ml1.x - gmax);
    const float e2 = has3 ? __expf(ml2.x - gmax) : 0.0f;

    float ll  = ml0.y * e0 + ml1.y * e1 + ml2.y * e2;
    float acc = r0 * e0 + r1 * e1 + r2 * e2;
    #pragma unroll
    for (int off = 16; off > 0; off >>= 1) {
        ll  += __shfl_xor_sync(0xffffffffu, ll,  off);
        acc += __shfl_xor_sync(0xffffffffu, acc, off);
    }
    if (lane == 0) { s8l[warp] = ll; s8a[warp] = acc; }
    __syncthreads();
    if (t == 0) {
        const float L = ((s8l[0] + s8l[1]) + (s8l[2] + s8l[3]))
                      + ((s8l[4] + s8l[5]) + (s8l[6] + s8l[7]));
        const float A = ((s8a[0] + s8a[1]) + (s8a[2] + s8a[3]))
                      + ((s8a[4] + s8a[5]) + (s8a[6] + s8a[7]));
        out[c] = A / L;
    }
}

extern "C" void kernel_launch(void* const* d_in, const int* in_sizes, int n_in,
                              void* d_out, int out_size) {
    const float* q = (const float*)d_in[0];
    const float* K = (const float*)d_in[1];
    const float* V = (const float*)d_in[2];
    float* out = (float*)d_out;

    sqa_pass1<<<NCTA, 256>>>(q, K, V);
    sqa_tail<<<DIM, 256>>>(out);
}